// round 10
// baseline (speedup 1.0000x reference)
#include <cuda_runtime.h>
#include <cuda_bf16.h>
#include <cstdint>

#define N_NODES 100000
#define N_EDGES 1600000
#define IN_DIM 128
#define EDGE_DIM 64
#define HD 64
#define OUT_DIM 8
#define TILE_E 64
#define QKV_NODES 16
#define PITCH_T 68
#define KPH 32              // k per phase in edge GEMM

__device__ __forceinline__ void upk2(unsigned long long v, float& lo, float& hi) {
    asm("mov.b64 {%0, %1}, %2;" : "=f"(lo), "=f"(hi) : "l"(v));
}
#define FFMA2(d, a, b) asm("fma.rn.f32x2 %0, %1, %2, %0;" : "+l"(d) : "l"(a), "l"(b))

// ---------------- scratch ----------------------------------------------------
__device__ float g_Q[(size_t)N_NODES * HD];
__device__ float g_K[(size_t)N_NODES * HD];
__device__ float g_VW[(size_t)N_NODES * HD];   // (V @ Wo) per head: [n][h][j]
__device__ float g_sum[(size_t)N_NODES * OUT_DIM];
__device__ int   g_cnt[N_NODES];
__device__ int   g_i64flag;

__global__ void zero_kernel() {
    int i = blockIdx.x * blockDim.x + threadIdx.x;
    if (i < N_NODES * OUT_DIM) g_sum[i] = 0.f;
    if (i < N_NODES) g_cnt[i] = 0;
}

__global__ void detect_kernel(const void* ei) {
    if (threadIdx.x == 0 && blockIdx.x == 0) {
        const unsigned long long* p = (const unsigned long long*)ei;
        int is64 = 1;
        for (int i = 0; i < 64; i++)
            if (p[i] >= (unsigned long long)N_NODES) { is64 = 0; break; }
        g_i64flag = is64;
    }
}

// ---------------- QKV projection + fused VW = V @ Wo (per head) --------------
__global__ __launch_bounds__(192) void qkv_kernel(
    const float* __restrict__ x,
    const float* __restrict__ Wq, const float* __restrict__ bq,
    const float* __restrict__ Wk, const float* __restrict__ bk,
    const float* __restrict__ Wv, const float* __restrict__ bv,
    const float* __restrict__ Wo)
{
    __shared__ float xs[QKV_NODES][IN_DIM];
    __shared__ float xv[QKV_NODES][HD + 1];
    __shared__ float swo[HD * 9];
    const int nb = blockIdx.x * QKV_NODES;
    const int t = threadIdx.x;

    for (int i = t; i < HD * OUT_DIM; i += 192) swo[(i >> 3) * 9 + (i & 7)] = Wo[i];
    for (int i = t; i < QKV_NODES * (IN_DIM / 4); i += 192) {
        int n = i >> 5, kk = i & 31;
        *(float4*)&xs[n][kk * 4] =
            *(const float4*)&x[(size_t)(nb + n) * IN_DIM + kk * 4];
    }
    __syncthreads();

    const int m = t >> 6, c = t & 63;
    const float* W = (m == 0) ? Wq : (m == 1) ? Wk : Wv;
    const float* b = (m == 0) ? bq : (m == 1) ? bk : bv;

    float acc[QKV_NODES];
#pragma unroll
    for (int n = 0; n < QKV_NODES; n++) acc[n] = 0.f;

#pragma unroll 2
    for (int k = 0; k < IN_DIM; k += 4) {
        float w0 = W[(k + 0) * HD + c];
        float w1 = W[(k + 1) * HD + c];
        float w2 = W[(k + 2) * HD + c];
        float w3 = W[(k + 3) * HD + c];
#pragma unroll
        for (int n = 0; n < QKV_NODES; n++) {
            float4 xvv = *(const float4*)&xs[n][k];
            acc[n] = fmaf(xvv.x, w0, fmaf(xvv.y, w1,
                     fmaf(xvv.z, w2, fmaf(xvv.w, w3, acc[n]))));
        }
    }
    const float bc = b[c];
    if (m == 2) {
#pragma unroll
        for (int n = 0; n < QKV_NODES; n++) xv[n][c] = acc[n] + bc;
    } else {
        float* dstp = (m == 0) ? g_Q : g_K;
#pragma unroll
        for (int n = 0; n < QKV_NODES; n++)
            dstp[(size_t)(nb + n) * HD + c] = acc[n] + bc;
    }
    __syncthreads();

    for (int i = t; i < QKV_NODES * HD; i += 192) {
        int n = i >> 6, cc = i & 63;
        int h8 = cc & 56, j = cc & 7;
        const float* vr = &xv[n][h8];
        const float* wr = &swo[h8 * 9 + j];
        float s = 0.f;
#pragma unroll
        for (int d = 0; d < 8; d++) s = fmaf(vr[d], wr[d * 9], s);
        g_VW[(size_t)(nb + n) * HD + cc] = s;
    }
}

// ---------------- per-edge kernel --------------------------------------------
// 128 threads, tile = 64 edges. thread (eg = t>>3, h = t&7): edges eg*4..+3,
// head h. GEMM uses f32x2 packed over edge pairs; B duplicated in smem.
__global__ __launch_bounds__(128) void edge_kernel(
    const float* __restrict__ edge_attr,
    const float* __restrict__ We, const float* __restrict__ be,
    const void* __restrict__ ei)
{
    __shared__ float sWd[EDGE_DIM * 128];    // [k][jj][h]: (w2jj,w2jj,w2jj+1,w2jj+1), 32KB
    __shared__ float seaT[KPH * PITCH_T];    // [k-local][e], swizzled, one phase

    const int t = threadIdx.x;
    const int h = t & 7;
    const int eg = t >> 3;
    const int ebase = eg * 4;
    const int is64 = g_i64flag;

    // stage duplicated We: element (k, c=h*8+2jj+w) -> sWd[k*128 + jj*32 + h*4 + w*2 {,+1}]
    for (int i = t; i < EDGE_DIM * HD; i += 128) {
        int k = i >> 6, c = i & 63;
        int hh = c >> 3, cc = c & 7;
        int jj = cc >> 1, w = cc & 1;
        float v = We[k * HD + c];
        int base = k * 128 + jj * 32 + hh * 4 + w * 2;
        sWd[base] = v;
        sWd[base + 1] = v;
    }
    // this head's bias in registers
    float4 be0 = *(const float4*)&be[h * 8];
    float4 be1 = *(const float4*)&be[h * 8 + 4];
    __syncthreads();

    const int ntiles = N_EDGES / TILE_E;
    for (int tile = blockIdx.x; tile < ntiles; tile += gridDim.x) {
        const int e0 = tile * TILE_E;

        int src[4], dst[4];
        if (is64) {
            const longlong2* ps = (const longlong2*)((const long long*)ei + (e0 + ebase));
            const longlong2* pd = (const longlong2*)((const long long*)ei + N_EDGES + (e0 + ebase));
            longlong2 s01 = ps[0], s23 = ps[1], d01 = pd[0], d23 = pd[1];
            src[0] = (int)s01.x; src[1] = (int)s01.y; src[2] = (int)s23.x; src[3] = (int)s23.y;
            dst[0] = (int)d01.x; dst[1] = (int)d01.y; dst[2] = (int)d23.x; dst[3] = (int)d23.y;
        } else {
            int4 s = *(const int4*)((const int*)ei + (e0 + ebase));
            int4 d = *(const int4*)((const int*)ei + N_EDGES + (e0 + ebase));
            src[0] = s.x; src[1] = s.y; src[2] = s.z; src[3] = s.w;
            dst[0] = d.x; dst[1] = d.y; dst[2] = d.z; dst[3] = d.w;
        }

        // early Q/K gathers (L2-resident), folded to scalars before the GEMM
        float4 q0[4], q1[4], k0[4], k1[4];
#pragma unroll
        for (int i = 0; i < 4; i++) {
            const float4* qp = (const float4*)(g_Q + (size_t)src[i] * HD + h * 8);
            const float4* kp = (const float4*)(g_K + (size_t)dst[i] * HD + h * 8);
            q0[i] = qp[0]; q1[i] = qp[1];
            k0[i] = kp[0]; k1[i] = kp[1];
        }
        float qk[4];
#pragma unroll
        for (int i = 0; i < 4; i++) {
            qk[i] = q0[i].x * k0[i].x + q0[i].y * k0[i].y
                  + q0[i].z * k0[i].z + q0[i].w * k0[i].w
                  + q1[i].x * k1[i].x + q1[i].y * k1[i].y
                  + q1[i].z * k1[i].z + q1[i].w * k1[i].w;
        }

        // f32x2 accumulators: acc2[p][cc] = cols cc of edges (ebase+2p, ebase+2p+1)
        unsigned long long acc2[2][8];
#pragma unroll
        for (int p = 0; p < 2; p++)
#pragma unroll
            for (int cc = 0; cc < 8; cc++) acc2[p][cc] = 0ull;

#pragma unroll
        for (int ph = 0; ph < 2; ph++) {
            // stage 32 k-rows of edge_attr, transposed + swizzled
            for (int i = t; i < TILE_E * (KPH / 4); i += 128) {
                int k4l = i & 7;                  // 0..7 within phase
                int e = (i >> 3) & 63;
                int k4 = ph * 8 + k4l;
                float4 v = *(const float4*)&edge_attr[(size_t)(e0 + e) * EDGE_DIM + k4 * 4];
                int col = e ^ (k4l << 2);
                int base = k4l * 4;
                seaT[(base + 0) * PITCH_T + col] = v.x;
                seaT[(base + 1) * PITCH_T + col] = v.y;
                seaT[(base + 2) * PITCH_T + col] = v.z;
                seaT[(base + 3) * PITCH_T + col] = v.w;
            }
            __syncthreads();

#pragma unroll 8
            for (int k = 0; k < KPH; k++) {
                const int kg = ph * KPH + k;
                int col = ebase ^ (((k >> 2) & 7) << 2);
                ulonglong2 A2 = *(const ulonglong2*)&seaT[k * PITCH_T + col];
                const float* bp = &sWd[kg * 128 + h * 4];
                ulonglong2 B0 = *(const ulonglong2*)&bp[0];      // cols 0,1 dup'd
                ulonglong2 B1 = *(const ulonglong2*)&bp[32];     // cols 2,3
                ulonglong2 B2 = *(const ulonglong2*)&bp[64];     // cols 4,5
                ulonglong2 B3 = *(const ulonglong2*)&bp[96];     // cols 6,7
                FFMA2(acc2[0][0], A2.x, B0.x); FFMA2(acc2[0][1], A2.x, B0.y);
                FFMA2(acc2[0][2], A2.x, B1.x); FFMA2(acc2[0][3], A2.x, B1.y);
                FFMA2(acc2[0][4], A2.x, B2.x); FFMA2(acc2[0][5], A2.x, B2.y);
                FFMA2(acc2[0][6], A2.x, B3.x); FFMA2(acc2[0][7], A2.x, B3.y);
                FFMA2(acc2[1][0], A2.y, B0.x); FFMA2(acc2[1][1], A2.y, B0.y);
                FFMA2(acc2[1][2], A2.y, B1.x); FFMA2(acc2[1][3], A2.y, B1.y);
                FFMA2(acc2[1][4], A2.y, B2.x); FFMA2(acc2[1][5], A2.y, B2.y);
                FFMA2(acc2[1][6], A2.y, B3.x); FFMA2(acc2[1][7], A2.y, B3.y);
            }
            __syncthreads();
        }

        // prefetch VW gathers
        float4 vw0[4], vw1[4];
#pragma unroll
        for (int i = 0; i < 4; i++) {
            const float4* vp = (const float4*)(g_VW + (size_t)dst[i] * HD + h * 8);
            vw0[i] = vp[0]; vw1[i] = vp[1];
        }

        const float inv_sqrt_d = 0.35355339059327373f;
#pragma unroll
        for (int i = 0; i < 4; i++) {
            const int p = i >> 1;
            const int b = i & 1;
            float E0, E1, E2, E3, E4, E5, E6, E7, dummy;
            if (b == 0) {
                upk2(acc2[p][0], E0, dummy); upk2(acc2[p][1], E1, dummy);
                upk2(acc2[p][2], E2, dummy); upk2(acc2[p][3], E3, dummy);
                upk2(acc2[p][4], E4, dummy); upk2(acc2[p][5], E5, dummy);
                upk2(acc2[p][6], E6, dummy); upk2(acc2[p][7], E7, dummy);
            } else {
                upk2(acc2[p][0], dummy, E0); upk2(acc2[p][1], dummy, E1);
                upk2(acc2[p][2], dummy, E2); upk2(acc2[p][3], dummy, E3);
                upk2(acc2[p][4], dummy, E4); upk2(acc2[p][5], dummy, E5);
                upk2(acc2[p][6], dummy, E6); upk2(acc2[p][7], dummy, E7);
            }
            float s = qk[i];
            float v;
            v = E0 + be0.x; s = fmaf(v, v, s);
            v = E1 + be0.y; s = fmaf(v, v, s);
            v = E2 + be0.z; s = fmaf(v, v, s);
            v = E3 + be0.w; s = fmaf(v, v, s);
            v = E4 + be1.x; s = fmaf(v, v, s);
            v = E5 + be1.y; s = fmaf(v, v, s);
            v = E6 + be1.z; s = fmaf(v, v, s);
            v = E7 + be1.w; s = fmaf(v, v, s);
            s *= inv_sqrt_d;

            // softmax over the 8 head lanes
            float m = s;
            m = fmaxf(m, __shfl_xor_sync(0xffffffffu, m, 1));
            m = fmaxf(m, __shfl_xor_sync(0xffffffffu, m, 2));
            m = fmaxf(m, __shfl_xor_sync(0xffffffffu, m, 4));
            float ex = __expf(s - m);
            float sum = ex;
            sum += __shfl_xor_sync(0xffffffffu, sum, 1);
            sum += __shfl_xor_sync(0xffffffffu, sum, 2);
            sum += __shfl_xor_sync(0xffffffffu, sum, 4);
            float wgt = ex / sum;

            // p[j] = wgt * VW[dst][h][j]; reduce-scatter over 8 head lanes
            float p8[8] = { wgt * vw0[i].x, wgt * vw0[i].y, wgt * vw0[i].z, wgt * vw0[i].w,
                            wgt * vw1[i].x, wgt * vw1[i].y, wgt * vw1[i].z, wgt * vw1[i].w };
            bool hi4 = (h & 4) != 0;
            float t0 = hi4 ? p8[0] : p8[4];
            float t1 = hi4 ? p8[1] : p8[5];
            float t2 = hi4 ? p8[2] : p8[6];
            float t3 = hi4 ? p8[3] : p8[7];
            t0 = __shfl_xor_sync(0xffffffffu, t0, 4);
            t1 = __shfl_xor_sync(0xffffffffu, t1, 4);
            t2 = __shfl_xor_sync(0xffffffffu, t2, 4);
            t3 = __shfl_xor_sync(0xffffffffu, t3, 4);
            float q0r = (hi4 ? p8[4] : p8[0]) + t0;
            float q1r = (hi4 ? p8[5] : p8[1]) + t1;
            float q2r = (hi4 ? p8[6] : p8[2]) + t2;
            float q3r = (hi4 ? p8[7] : p8[3]) + t3;
            bool hi2 = (h & 2) != 0;
            float u0 = hi2 ? q0r : q2r;
            float u1 = hi2 ? q1r : q3r;
            u0 = __shfl_xor_sync(0xffffffffu, u0, 2);
            u1 = __shfl_xor_sync(0xffffffffu, u1, 2);
            float r0 = (hi2 ? q2r : q0r) + u0;
            float r1 = (hi2 ? q3r : q1r) + u1;
            bool hi1 = (h & 1) != 0;
            float w0s = hi1 ? r0 : r1;
            w0s = __shfl_xor_sync(0xffffffffu, w0s, 1);
            float res = (hi1 ? r1 : r0) + w0s;

            atomicAdd(&g_sum[(size_t)src[i] * OUT_DIM + h], res);
            if (h == 0) atomicAdd(&g_cnt[src[i]], 1);
        }
    }
}

__global__ void finalize_kernel(float* __restrict__ out, const float* __restrict__ bo) {
    int i = blockIdx.x * blockDim.x + threadIdx.x;
    if (i < N_NODES * OUT_DIM) {
        int n = i >> 3, j = i & 7;
        int c = g_cnt[n];
        float r = 0.f;
        if (c > 0) r = g_sum[i] / (float)c + bo[j];
        out[i] = r;
    }
}

extern "C" void kernel_launch(void* const* d_in, const int* in_sizes, int n_in,
                              void* d_out, int out_size)
{
    const float* x  = (const float*)d_in[0];
    const float* ea = (const float*)d_in[1];
    const float* Wq = (const float*)d_in[2];
    const float* bq = (const float*)d_in[3];
    const float* Wk = (const float*)d_in[4];
    const float* bk = (const float*)d_in[5];
    const float* Wv = (const float*)d_in[6];
    const float* bv = (const float*)d_in[7];
    const float* We = (const float*)d_in[8];
    const float* be = (const float*)d_in[9];
    const float* Wo = (const float*)d_in[10];
    const float* bo = (const float*)d_in[11];
    const void*  ei = d_in[12];
    float* out = (float*)d_out;

    zero_kernel<<<(N_NODES * OUT_DIM + 255) / 256, 256>>>();
    detect_kernel<<<1, 32>>>(ei);
    qkv_kernel<<<N_NODES / QKV_NODES, 192>>>(x, Wq, bq, Wk, bk, Wv, bv, Wo);
    edge_kernel<<<1184, 128>>>(ea, We, be, ei);
    finalize_kernel<<<(N_NODES * OUT_DIM + 255) / 256, 256>>>(out, bo);
}

// round 11
// speedup vs baseline: 1.5622x; 1.5622x over previous
#include <cuda_runtime.h>
#include <cuda_bf16.h>
#include <cstdint>

#define N_NODES 100000
#define N_EDGES 1600000
#define IN_DIM 128
#define EDGE_DIM 64
#define HD 64
#define OUT_DIM 8
#define TILE_E 64
#define QKV_NODES 16
#define PITCH_A 68          // sea row pitch (uint32 words)

// ---------------- scratch ----------------------------------------------------
__device__ float g_Q[(size_t)N_NODES * HD];
__device__ float g_K[(size_t)N_NODES * HD];
__device__ float g_VW[(size_t)N_NODES * HD];   // (V @ Wo) per head: [n][h][j]
__device__ float g_sum[(size_t)N_NODES * OUT_DIM];
__device__ int   g_cnt[N_NODES];
__device__ int   g_i64flag;

__device__ __forceinline__ uint32_t f2tf32(float f) {
    uint32_t r;
    asm("cvt.rna.tf32.f32 %0, %1;" : "=r"(r) : "f"(f));
    return r;
}
__device__ __forceinline__ void mma_tf32(
    float& d0, float& d1, float& d2, float& d3,
    uint32_t a0, uint32_t a1, uint32_t a2, uint32_t a3,
    uint32_t b0, uint32_t b1)
{
    asm("mma.sync.aligned.m16n8k8.row.col.f32.tf32.tf32.f32 "
        "{%0,%1,%2,%3}, {%4,%5,%6,%7}, {%8,%9}, {%0,%1,%2,%3};"
        : "+f"(d0), "+f"(d1), "+f"(d2), "+f"(d3)
        : "r"(a0), "r"(a1), "r"(a2), "r"(a3), "r"(b0), "r"(b1));
}

__global__ void zero_kernel() {
    int i = blockIdx.x * blockDim.x + threadIdx.x;
    if (i < N_NODES * OUT_DIM) g_sum[i] = 0.f;
    if (i < N_NODES) g_cnt[i] = 0;
}

__global__ void detect_kernel(const void* ei) {
    if (threadIdx.x == 0 && blockIdx.x == 0) {
        const unsigned long long* p = (const unsigned long long*)ei;
        int is64 = 1;
        for (int i = 0; i < 64; i++)
            if (p[i] >= (unsigned long long)N_NODES) { is64 = 0; break; }
        g_i64flag = is64;
    }
}

// ---------------- QKV projection + fused VW = V @ Wo (per head) --------------
__global__ __launch_bounds__(192) void qkv_kernel(
    const float* __restrict__ x,
    const float* __restrict__ Wq, const float* __restrict__ bq,
    const float* __restrict__ Wk, const float* __restrict__ bk,
    const float* __restrict__ Wv, const float* __restrict__ bv,
    const float* __restrict__ Wo)
{
    __shared__ float xs[QKV_NODES][IN_DIM];
    __shared__ float xv[QKV_NODES][HD + 1];
    __shared__ float swo[HD * 9];
    const int nb = blockIdx.x * QKV_NODES;
    const int t = threadIdx.x;

    for (int i = t; i < HD * OUT_DIM; i += 192) swo[(i >> 3) * 9 + (i & 7)] = Wo[i];
    for (int i = t; i < QKV_NODES * (IN_DIM / 4); i += 192) {
        int n = i >> 5, kk = i & 31;
        *(float4*)&xs[n][kk * 4] =
            *(const float4*)&x[(size_t)(nb + n) * IN_DIM + kk * 4];
    }
    __syncthreads();

    const int m = t >> 6, c = t & 63;
    const float* W = (m == 0) ? Wq : (m == 1) ? Wk : Wv;
    const float* b = (m == 0) ? bq : (m == 1) ? bk : bv;

    float acc[QKV_NODES];
#pragma unroll
    for (int n = 0; n < QKV_NODES; n++) acc[n] = 0.f;

#pragma unroll 2
    for (int k = 0; k < IN_DIM; k += 4) {
        float w0 = W[(k + 0) * HD + c];
        float w1 = W[(k + 1) * HD + c];
        float w2 = W[(k + 2) * HD + c];
        float w3 = W[(k + 3) * HD + c];
#pragma unroll
        for (int n = 0; n < QKV_NODES; n++) {
            float4 xvv = *(const float4*)&xs[n][k];
            acc[n] = fmaf(xvv.x, w0, fmaf(xvv.y, w1,
                     fmaf(xvv.z, w2, fmaf(xvv.w, w3, acc[n]))));
        }
    }
    const float bc = b[c];
    if (m == 2) {
#pragma unroll
        for (int n = 0; n < QKV_NODES; n++) xv[n][c] = acc[n] + bc;
    } else {
        float* dstp = (m == 0) ? g_Q : g_K;
#pragma unroll
        for (int n = 0; n < QKV_NODES; n++)
            dstp[(size_t)(nb + n) * HD + c] = acc[n] + bc;
    }
    __syncthreads();

    for (int i = t; i < QKV_NODES * HD; i += 192) {
        int n = i >> 6, cc = i & 63;
        int h8 = cc & 56, j = cc & 7;
        const float* vr = &xv[n][h8];
        const float* wr = &swo[h8 * 9 + j];
        float s = 0.f;
#pragma unroll
        for (int d = 0; d < 8; d++) s = fmaf(vr[d], wr[d * 9], s);
        g_VW[(size_t)(nb + n) * HD + cc] = s;
    }
}

// ---------------- per-edge kernel --------------------------------------------
// 128 threads, tile = 64 edges.
// GEMM phase: warp w computes E-scores for edges w*16..w*16+15, all 8 heads,
//   via tf32 mma.sync (16x8 D tile per head), writing sum((E+be)^2) to ssc.
// Epilogue: thread (eg = t>>3, h = t&7) handles edges eg*4..+3 head h,
//   identical to the proven scalar version (qk + softmax + VW + scatter).
__global__ __launch_bounds__(128) void edge_kernel(
    const float* __restrict__ edge_attr,
    const float* __restrict__ We, const float* __restrict__ be,
    const void* __restrict__ ei)
{
    __shared__ uint2    sBf[64 * 32];          // B fragments: [(h*8+q)][lane], 16KB
    __shared__ uint32_t sea[TILE_E * PITCH_A]; // A tile, tf32-converted, 17.4KB
    __shared__ float    ssc[TILE_E * 8];       // scores (E+be)^2 sums, 2KB
    __shared__ float    sbe[HD];

    const int t = threadIdx.x;
    const int lane = t & 31;
    const int g = lane >> 2;
    const int c = lane & 3;
    const int wbase = (t >> 5) * 16;
    const int h = t & 7;
    const int eg = t >> 3;
    const int ebase = eg * 4;
    const int is64 = g_i64flag;

    // pack We into mma B-fragment order (tf32), once per block
    for (int i = t; i < 64 * 32; i += 128) {
        int hq = i >> 5, ln = i & 31;
        int hh = hq >> 3, q = hq & 7;
        int gg = ln >> 2, cc = ln & 3;
        float w0 = We[(8 * q + cc) * HD + 8 * hh + gg];
        float w1 = We[(8 * q + cc + 4) * HD + 8 * hh + gg];
        sBf[i] = make_uint2(f2tf32(w0), f2tf32(w1));
    }
    if (t < HD) sbe[t] = be[t];
    __syncthreads();

    const int ntiles = N_EDGES / TILE_E;
    for (int tile = blockIdx.x; tile < ntiles; tile += gridDim.x) {
        const int e0 = tile * TILE_E;

        int src[4], dst[4];
        if (is64) {
            const longlong2* ps = (const longlong2*)((const long long*)ei + (e0 + ebase));
            const longlong2* pd = (const longlong2*)((const long long*)ei + N_EDGES + (e0 + ebase));
            longlong2 s01 = ps[0], s23 = ps[1], d01 = pd[0], d23 = pd[1];
            src[0] = (int)s01.x; src[1] = (int)s01.y; src[2] = (int)s23.x; src[3] = (int)s23.y;
            dst[0] = (int)d01.x; dst[1] = (int)d01.y; dst[2] = (int)d23.x; dst[3] = (int)d23.y;
        } else {
            int4 s = *(const int4*)((const int*)ei + (e0 + ebase));
            int4 d = *(const int4*)((const int*)ei + N_EDGES + (e0 + ebase));
            src[0] = s.x; src[1] = s.y; src[2] = s.z; src[3] = s.w;
            dst[0] = d.x; dst[1] = d.y; dst[2] = d.z; dst[3] = d.w;
        }

        // early Q/K gathers (L2-resident), folded before the mma phase
        float4 q0[4], q1[4], k0[4], k1[4];
#pragma unroll
        for (int i = 0; i < 4; i++) {
            const float4* qp = (const float4*)(g_Q + (size_t)src[i] * HD + h * 8);
            const float4* kp = (const float4*)(g_K + (size_t)dst[i] * HD + h * 8);
            q0[i] = qp[0]; q1[i] = qp[1];
            k0[i] = kp[0]; k1[i] = kp[1];
        }

        // stage edge_attr tile, tf32-converted (row-major, pitch 68)
        for (int i = t; i < TILE_E * 16; i += 128) {
            int e = i >> 4, k4 = i & 15;
            float4 v = *(const float4*)&edge_attr[(size_t)(e0 + e) * EDGE_DIM + k4 * 4];
            uint32_t* dstw = &sea[e * PITCH_A + k4 * 4];
            dstw[0] = f2tf32(v.x);
            dstw[1] = f2tf32(v.y);
            dstw[2] = f2tf32(v.z);
            dstw[3] = f2tf32(v.w);
        }

        float qk[4];
#pragma unroll
        for (int i = 0; i < 4; i++) {
            qk[i] = q0[i].x * k0[i].x + q0[i].y * k0[i].y
                  + q0[i].z * k0[i].z + q0[i].w * k0[i].w
                  + q1[i].x * k1[i].x + q1[i].y * k1[i].y
                  + q1[i].z * k1[i].z + q1[i].w * k1[i].w;
        }
        __syncthreads();

        // ---- mma phase: load A fragments (conflict-free scalar LDS) ----
        uint32_t afr[8][4];
#pragma unroll
        for (int q = 0; q < 8; q++) {
            const uint32_t* r0 = &sea[(wbase + g) * PITCH_A + 8 * q];
            const uint32_t* r1 = &sea[(wbase + g + 8) * PITCH_A + 8 * q];
            afr[q][0] = r0[c];
            afr[q][1] = r1[c];
            afr[q][2] = r0[c + 4];
            afr[q][3] = r1[c + 4];
        }

#pragma unroll
        for (int hh = 0; hh < 8; hh++) {
            float d0 = 0.f, d1 = 0.f, d2 = 0.f, d3 = 0.f;
#pragma unroll
            for (int q = 0; q < 8; q++) {
                uint2 b = sBf[(hh * 8 + q) * 32 + lane];
                mma_tf32(d0, d1, d2, d3,
                         afr[q][0], afr[q][1], afr[q][2], afr[q][3], b.x, b.y);
            }
            float2 bev = *(const float2*)&sbe[8 * hh + 2 * c];
            float e00 = d0 + bev.x, e01 = d1 + bev.y;
            float e10 = d2 + bev.x, e11 = d3 + bev.y;
            float p0 = e00 * e00 + e01 * e01;   // edge wbase+g
            float p1 = e10 * e10 + e11 * e11;   // edge wbase+g+8
            p0 += __shfl_xor_sync(0xffffffffu, p0, 1);
            p0 += __shfl_xor_sync(0xffffffffu, p0, 2);
            p1 += __shfl_xor_sync(0xffffffffu, p1, 1);
            p1 += __shfl_xor_sync(0xffffffffu, p1, 2);
            if (c == 0) {
                ssc[(wbase + g) * 8 + hh] = p0;
                ssc[(wbase + g + 8) * 8 + hh] = p1;
            }
        }
        __syncthreads();

        // ---- epilogue (proven R7 structure) ----
        float4 vw0[4], vw1[4];
#pragma unroll
        for (int i = 0; i < 4; i++) {
            const float4* vp = (const float4*)(g_VW + (size_t)dst[i] * HD + h * 8);
            vw0[i] = vp[0]; vw1[i] = vp[1];
        }

        const float inv_sqrt_d = 0.35355339059327373f;
#pragma unroll
        for (int i = 0; i < 4; i++) {
            float s = (qk[i] + ssc[(ebase + i) * 8 + h]) * inv_sqrt_d;

            float m = s;
            m = fmaxf(m, __shfl_xor_sync(0xffffffffu, m, 1));
            m = fmaxf(m, __shfl_xor_sync(0xffffffffu, m, 2));
            m = fmaxf(m, __shfl_xor_sync(0xffffffffu, m, 4));
            float ex = __expf(s - m);
            float sum = ex;
            sum += __shfl_xor_sync(0xffffffffu, sum, 1);
            sum += __shfl_xor_sync(0xffffffffu, sum, 2);
            sum += __shfl_xor_sync(0xffffffffu, sum, 4);
            float wgt = ex / sum;

            float p8[8] = { wgt * vw0[i].x, wgt * vw0[i].y, wgt * vw0[i].z, wgt * vw0[i].w,
                            wgt * vw1[i].x, wgt * vw1[i].y, wgt * vw1[i].z, wgt * vw1[i].w };
            bool hi4 = (h & 4) != 0;
            float t0 = hi4 ? p8[0] : p8[4];
            float t1 = hi4 ? p8[1] : p8[5];
            float t2 = hi4 ? p8[2] : p8[6];
            float t3 = hi4 ? p8[3] : p8[7];
            t0 = __shfl_xor_sync(0xffffffffu, t0, 4);
            t1 = __shfl_xor_sync(0xffffffffu, t1, 4);
            t2 = __shfl_xor_sync(0xffffffffu, t2, 4);
            t3 = __shfl_xor_sync(0xffffffffu, t3, 4);
            float q0r = (hi4 ? p8[4] : p8[0]) + t0;
            float q1r = (hi4 ? p8[5] : p8[1]) + t1;
            float q2r = (hi4 ? p8[6] : p8[2]) + t2;
            float q3r = (hi4 ? p8[7] : p8[3]) + t3;
            bool hi2 = (h & 2) != 0;
            float u0 = hi2 ? q0r : q2r;
            float u1 = hi2 ? q1r : q3r;
            u0 = __shfl_xor_sync(0xffffffffu, u0, 2);
            u1 = __shfl_xor_sync(0xffffffffu, u1, 2);
            float r0 = (hi2 ? q2r : q0r) + u0;
            float r1 = (hi2 ? q3r : q1r) + u1;
            bool hi1 = (h & 1) != 0;
            float w0s = hi1 ? r0 : r1;
            w0s = __shfl_xor_sync(0xffffffffu, w0s, 1);
            float res = (hi1 ? r1 : r0) + w0s;

            atomicAdd(&g_sum[(size_t)src[i] * OUT_DIM + h], res);
            if (h == 0) atomicAdd(&g_cnt[src[i]], 1);
        }
    }
}

__global__ void finalize_kernel(float* __restrict__ out, const float* __restrict__ bo) {
    int i = blockIdx.x * blockDim.x + threadIdx.x;
    if (i < N_NODES * OUT_DIM) {
        int n = i >> 3, j = i & 7;
        int c = g_cnt[n];
        float r = 0.f;
        if (c > 0) r = g_sum[i] / (float)c + bo[j];
        out[i] = r;
    }
}

extern "C" void kernel_launch(void* const* d_in, const int* in_sizes, int n_in,
                              void* d_out, int out_size)
{
    const float* x  = (const float*)d_in[0];
    const float* ea = (const float*)d_in[1];
    const float* Wq = (const float*)d_in[2];
    const float* bq = (const float*)d_in[3];
    const float* Wk = (const float*)d_in[4];
    const float* bk = (const float*)d_in[5];
    const float* Wv = (const float*)d_in[6];
    const float* bv = (const float*)d_in[7];
    const float* We = (const float*)d_in[8];
    const float* be = (const float*)d_in[9];
    const float* Wo = (const float*)d_in[10];
    const float* bo = (const float*)d_in[11];
    const void*  ei = d_in[12];
    float* out = (float*)d_out;

    zero_kernel<<<(N_NODES * OUT_DIM + 255) / 256, 256>>>();
    detect_kernel<<<1, 32>>>(ei);
    qkv_kernel<<<N_NODES / QKV_NODES, 192>>>(x, Wq, bq, Wk, bk, Wv, bv, Wo);
    edge_kernel<<<1184, 128>>>(ea, We, be, ei);
    finalize_kernel<<<(N_NODES * OUT_DIM + 255) / 256, 256>>>(out, bo);
}

// round 12
// speedup vs baseline: 1.6129x; 1.0325x over previous
#include <cuda_runtime.h>
#include <cuda_bf16.h>
#include <cstdint>

#define N_NODES 100000
#define N_EDGES 1600000
#define IN_DIM 128
#define EDGE_DIM 64
#define HD 64
#define OUT_DIM 8
#define TILE_E 64
#define QKV_NODES 16
#define PITCH_A 68          // sea row pitch (uint32 words)

// ---------------- scratch ----------------------------------------------------
__device__ float g_Q[(size_t)N_NODES * HD];
__device__ float g_K[(size_t)N_NODES * HD];
__device__ float g_VWT[(size_t)N_NODES * HD];  // (V @ Wo) transposed: [n][j][h]
__device__ float g_sum[(size_t)N_NODES * OUT_DIM];
__device__ int   g_cnt[N_NODES];
__device__ int   g_i64flag;

__device__ __forceinline__ uint32_t f2tf32(float f) {
    uint32_t r;
    asm("cvt.rna.tf32.f32 %0, %1;" : "=r"(r) : "f"(f));
    return r;
}
__device__ __forceinline__ void mma_tf32(
    float& d0, float& d1, float& d2, float& d3,
    uint32_t a0, uint32_t a1, uint32_t a2, uint32_t a3,
    uint32_t b0, uint32_t b1)
{
    asm("mma.sync.aligned.m16n8k8.row.col.f32.tf32.tf32.f32 "
        "{%0,%1,%2,%3}, {%4,%5,%6,%7}, {%8,%9}, {%0,%1,%2,%3};"
        : "+f"(d0), "+f"(d1), "+f"(d2), "+f"(d3)
        : "r"(a0), "r"(a1), "r"(a2), "r"(a3), "r"(b0), "r"(b1));
}

__global__ void zero_kernel() {
    int i = blockIdx.x * blockDim.x + threadIdx.x;
    if (i < N_NODES * OUT_DIM) g_sum[i] = 0.f;
    if (i < N_NODES) g_cnt[i] = 0;
}

__global__ void detect_kernel(const void* ei) {
    if (threadIdx.x == 0 && blockIdx.x == 0) {
        const unsigned long long* p = (const unsigned long long*)ei;
        int is64 = 1;
        for (int i = 0; i < 64; i++)
            if (p[i] >= (unsigned long long)N_NODES) { is64 = 0; break; }
        g_i64flag = is64;
    }
}

// ---------------- QKV projection + fused VWT = (V @ Wo)^T per node -----------
__global__ __launch_bounds__(192) void qkv_kernel(
    const float* __restrict__ x,
    const float* __restrict__ Wq, const float* __restrict__ bq,
    const float* __restrict__ Wk, const float* __restrict__ bk,
    const float* __restrict__ Wv, const float* __restrict__ bv,
    const float* __restrict__ Wo)
{
    __shared__ float xs[QKV_NODES][IN_DIM];
    __shared__ float xv[QKV_NODES][HD + 1];
    __shared__ float swo[HD * 9];
    const int nb = blockIdx.x * QKV_NODES;
    const int t = threadIdx.x;

    for (int i = t; i < HD * OUT_DIM; i += 192) swo[(i >> 3) * 9 + (i & 7)] = Wo[i];
    for (int i = t; i < QKV_NODES * (IN_DIM / 4); i += 192) {
        int n = i >> 5, kk = i & 31;
        *(float4*)&xs[n][kk * 4] =
            *(const float4*)&x[(size_t)(nb + n) * IN_DIM + kk * 4];
    }
    __syncthreads();

    const int m = t >> 6, c = t & 63;
    const float* W = (m == 0) ? Wq : (m == 1) ? Wk : Wv;
    const float* b = (m == 0) ? bq : (m == 1) ? bk : bv;

    float acc[QKV_NODES];
#pragma unroll
    for (int n = 0; n < QKV_NODES; n++) acc[n] = 0.f;

#pragma unroll 2
    for (int k = 0; k < IN_DIM; k += 4) {
        float w0 = W[(k + 0) * HD + c];
        float w1 = W[(k + 1) * HD + c];
        float w2 = W[(k + 2) * HD + c];
        float w3 = W[(k + 3) * HD + c];
#pragma unroll
        for (int n = 0; n < QKV_NODES; n++) {
            float4 xvv = *(const float4*)&xs[n][k];
            acc[n] = fmaf(xvv.x, w0, fmaf(xvv.y, w1,
                     fmaf(xvv.z, w2, fmaf(xvv.w, w3, acc[n]))));
        }
    }
    const float bc = b[c];
    if (m == 2) {
#pragma unroll
        for (int n = 0; n < QKV_NODES; n++) xv[n][c] = acc[n] + bc;
    } else {
        float* dstp = (m == 0) ? g_Q : g_K;
#pragma unroll
        for (int n = 0; n < QKV_NODES; n++)
            dstp[(size_t)(nb + n) * HD + c] = acc[n] + bc;
    }
    __syncthreads();

    // VWT[n][j*8+h] = sum_d V[n][h*8+d] * Wo[h*8+d][j]
    for (int i = t; i < QKV_NODES * HD; i += 192) {
        int n = i >> 6, cc = i & 63;
        int h = cc >> 3, j = cc & 7;
        const float* vr = &xv[n][h << 3];
        const float* wr = &swo[(h << 3) * 9 + j];
        float s = 0.f;
#pragma unroll
        for (int d = 0; d < 8; d++) s = fmaf(vr[d], wr[d * 9], s);
        g_VWT[(size_t)(nb + n) * HD + j * 8 + h] = s;
    }
}

// ---------------- per-edge kernel --------------------------------------------
// 128 threads, tile = 64 edges, three phases:
//   stage: edge_attr -> smem (tf32), qk dot -> ssc
//   mma:   warp w computes E for edges w*16..+15 all heads; adds sum((E+be)^2) to ssc
//   A:     2 threads/edge: softmax over 8 heads in registers -> swt
//   B:     thread (eg, j): out[e][j] = dot(wgt[e][:], VWT[dst][j][:]) -> atomics
__global__ __launch_bounds__(128) void edge_kernel(
    const float* __restrict__ edge_attr,
    const float* __restrict__ We, const float* __restrict__ be,
    const void* __restrict__ ei)
{
    __shared__ uint2    sBf[64 * 32];          // B fragments: [(h*8+q)][lane]
    __shared__ uint32_t sea[TILE_E * PITCH_A]; // A tile (tf32)
    __shared__ float    ssc[TILE_E * 9];       // scores: qk + sum((E+be)^2)
    __shared__ float    swt[TILE_E * 9];       // softmax weights
    __shared__ float    sbe[HD];

    const int t = threadIdx.x;
    const int lane = t & 31;
    const int g = lane >> 2;
    const int c = lane & 3;
    const int wbase = (t >> 5) * 16;
    const int h = t & 7;
    const int eg = t >> 3;
    const int ebase = eg * 4;
    const int is64 = g_i64flag;

    // pack We into mma B-fragment order (tf32), once per block
    for (int i = t; i < 64 * 32; i += 128) {
        int hq = i >> 5, ln = i & 31;
        int hh = hq >> 3, q = hq & 7;
        int gg = ln >> 2, cc = ln & 3;
        float w0 = We[(8 * q + cc) * HD + 8 * hh + gg];
        float w1 = We[(8 * q + cc + 4) * HD + 8 * hh + gg];
        sBf[i] = make_uint2(f2tf32(w0), f2tf32(w1));
    }
    if (t < HD) sbe[t] = be[t];
    __syncthreads();

    const float inv_sqrt_d = 0.35355339059327373f;
    const int ntiles = N_EDGES / TILE_E;
    for (int tile = blockIdx.x; tile < ntiles; tile += gridDim.x) {
        const int e0 = tile * TILE_E;

        int src[4], dst[4];
        if (is64) {
            const longlong2* ps = (const longlong2*)((const long long*)ei + (e0 + ebase));
            const longlong2* pd = (const longlong2*)((const long long*)ei + N_EDGES + (e0 + ebase));
            longlong2 s01 = ps[0], s23 = ps[1], d01 = pd[0], d23 = pd[1];
            src[0] = (int)s01.x; src[1] = (int)s01.y; src[2] = (int)s23.x; src[3] = (int)s23.y;
            dst[0] = (int)d01.x; dst[1] = (int)d01.y; dst[2] = (int)d23.x; dst[3] = (int)d23.y;
        } else {
            int4 s = *(const int4*)((const int*)ei + (e0 + ebase));
            int4 d = *(const int4*)((const int*)ei + N_EDGES + (e0 + ebase));
            src[0] = s.x; src[1] = s.y; src[2] = s.z; src[3] = s.w;
            dst[0] = d.x; dst[1] = d.y; dst[2] = d.z; dst[3] = d.w;
        }

        // Q/K gathers (L2-resident)
        float4 q0[4], q1[4], k0[4], k1[4];
#pragma unroll
        for (int i = 0; i < 4; i++) {
            const float4* qp = (const float4*)(g_Q + (size_t)src[i] * HD + h * 8);
            const float4* kp = (const float4*)(g_K + (size_t)dst[i] * HD + h * 8);
            q0[i] = qp[0]; q1[i] = qp[1];
            k0[i] = kp[0]; k1[i] = kp[1];
        }

        // stage edge_attr tile, tf32-converted
        for (int i = t; i < TILE_E * 16; i += 128) {
            int e = i >> 4, k4 = i & 15;
            float4 v = *(const float4*)&edge_attr[(size_t)(e0 + e) * EDGE_DIM + k4 * 4];
            uint32_t* dstw = &sea[e * PITCH_A + k4 * 4];
            dstw[0] = f2tf32(v.x);
            dstw[1] = f2tf32(v.y);
            dstw[2] = f2tf32(v.z);
            dstw[3] = f2tf32(v.w);
        }

        // fold qk and park in ssc (frees all gather registers before mma)
#pragma unroll
        for (int i = 0; i < 4; i++) {
            float qk = q0[i].x * k0[i].x + q0[i].y * k0[i].y
                     + q0[i].z * k0[i].z + q0[i].w * k0[i].w
                     + q1[i].x * k1[i].x + q1[i].y * k1[i].y
                     + q1[i].z * k1[i].z + q1[i].w * k1[i].w;
            ssc[(ebase + i) * 9 + h] = qk;
        }
        __syncthreads();

        // ---- mma phase ----
        uint32_t afr[8][4];
#pragma unroll
        for (int q = 0; q < 8; q++) {
            const uint32_t* r0 = &sea[(wbase + g) * PITCH_A + 8 * q];
            const uint32_t* r1 = &sea[(wbase + g + 8) * PITCH_A + 8 * q];
            afr[q][0] = r0[c];
            afr[q][1] = r1[c];
            afr[q][2] = r0[c + 4];
            afr[q][3] = r1[c + 4];
        }

#pragma unroll
        for (int hh = 0; hh < 8; hh++) {
            float d0 = 0.f, d1 = 0.f, d2 = 0.f, d3 = 0.f;
#pragma unroll
            for (int q = 0; q < 8; q++) {
                uint2 b = sBf[(hh * 8 + q) * 32 + lane];
                mma_tf32(d0, d1, d2, d3,
                         afr[q][0], afr[q][1], afr[q][2], afr[q][3], b.x, b.y);
            }
            float2 bev = *(const float2*)&sbe[8 * hh + 2 * c];
            float e00 = d0 + bev.x, e01 = d1 + bev.y;
            float e10 = d2 + bev.x, e11 = d3 + bev.y;
            float p0 = e00 * e00 + e01 * e01;   // edge wbase+g
            float p1 = e10 * e10 + e11 * e11;   // edge wbase+g+8
            p0 += __shfl_xor_sync(0xffffffffu, p0, 1);
            p0 += __shfl_xor_sync(0xffffffffu, p0, 2);
            p1 += __shfl_xor_sync(0xffffffffu, p1, 1);
            p1 += __shfl_xor_sync(0xffffffffu, p1, 2);
            if (c == 0) {
                ssc[(wbase + g) * 9 + hh] += p0;
                ssc[(wbase + g + 8) * 9 + hh] += p1;
            }
        }
        __syncthreads();

        // ---- phase A: softmax per edge (2 threads/edge, heads in registers) ----
        {
            int e = t >> 1;
            int hb = (t & 1) * 4;
            const float* sp = &ssc[e * 9 + hb];
            float s0 = sp[0] * inv_sqrt_d;
            float s1 = sp[1] * inv_sqrt_d;
            float s2 = sp[2] * inv_sqrt_d;
            float s3 = sp[3] * inv_sqrt_d;
            float mx = fmaxf(fmaxf(s0, s1), fmaxf(s2, s3));
            mx = fmaxf(mx, __shfl_xor_sync(0xffffffffu, mx, 1));
            float x0 = __expf(s0 - mx);
            float x1 = __expf(s1 - mx);
            float x2 = __expf(s2 - mx);
            float x3 = __expf(s3 - mx);
            float sm = (x0 + x1) + (x2 + x3);
            sm += __shfl_xor_sync(0xffffffffu, sm, 1);
            float inv = __fdividef(1.0f, sm);
            float* wp = &swt[e * 9 + hb];
            wp[0] = x0 * inv;
            wp[1] = x1 * inv;
            wp[2] = x2 * inv;
            wp[3] = x3 * inv;
        }
        __syncthreads();

        // ---- phase B: thread (eg, j) -> out[e][j] = dot(wgt[e], VWT[dst][j]) ----
        const int j = h;   // alias: same lane decomposition
        float4 a0[4], a1[4];
#pragma unroll
        for (int i = 0; i < 4; i++) {
            const float4* vp = (const float4*)(g_VWT + (size_t)dst[i] * HD + j * 8);
            a0[i] = vp[0]; a1[i] = vp[1];
        }
#pragma unroll
        for (int i = 0; i < 4; i++) {
            const float* wp = &swt[(ebase + i) * 9];
            float res = wp[0] * a0[i].x + wp[1] * a0[i].y
                      + wp[2] * a0[i].z + wp[3] * a0[i].w
                      + wp[4] * a1[i].x + wp[5] * a1[i].y
                      + wp[6] * a1[i].z + wp[7] * a1[i].w;
            atomicAdd(&g_sum[(size_t)src[i] * OUT_DIM + j], res);
        }
        if (j == 0) {
#pragma unroll
            for (int i = 0; i < 4; i++) atomicAdd(&g_cnt[src[i]], 1);
        }
    }
}

__global__ void finalize_kernel(float* __restrict__ out, const float* __restrict__ bo) {
    int i = blockIdx.x * blockDim.x + threadIdx.x;
    if (i < N_NODES * OUT_DIM) {
        int n = i >> 3, j = i & 7;
        int c = g_cnt[n];
        float r = 0.f;
        if (c > 0) r = g_sum[i] / (float)c + bo[j];
        out[i] = r;
    }
}

extern "C" void kernel_launch(void* const* d_in, const int* in_sizes, int n_in,
                              void* d_out, int out_size)
{
    const float* x  = (const float*)d_in[0];
    const float* ea = (const float*)d_in[1];
    const float* Wq = (const float*)d_in[2];
    const float* bq = (const float*)d_in[3];
    const float* Wk = (const float*)d_in[4];
    const float* bk = (const float*)d_in[5];
    const float* Wv = (const float*)d_in[6];
    const float* bv = (const float*)d_in[7];
    const float* We = (const float*)d_in[8];
    const float* be = (const float*)d_in[9];
    const float* Wo = (const float*)d_in[10];
    const float* bo = (const float*)d_in[11];
    const void*  ei = d_in[12];
    float* out = (float*)d_out;

    zero_kernel<<<(N_NODES * OUT_DIM + 255) / 256, 256>>>();
    detect_kernel<<<1, 32>>>(ei);
    qkv_kernel<<<N_NODES / QKV_NODES, 192>>>(x, Wq, bq, Wk, bk, Wv, bv, Wo);
    edge_kernel<<<1184, 128>>>(ea, We, be, ei);
    finalize_kernel<<<(N_NODES * OUT_DIM + 255) / 256, 256>>>(out, bo);
}